// round 6
// baseline (speedup 1.0000x reference)
#include <cuda_runtime.h>
#include <cstdint>

#define IMG_H 1024
#define IMG_W 1024
#define CHUNK 64             // output rows per warp
#define USEFUL 56            // output cols per warp (local cols 4..59)
#define NSTRIPS 19           // ceil(1024 / 56)
#define WPB 4                // warps per block

__constant__ int c_dy[8] = {0, 1, 1, 1, 0, -1, -1, -1};
__constant__ int c_dx[8] = {1, 1, 0, -1, -1, -1, 0, 1};

// identical chain to the passing kernels — do not touch
__device__ __forceinline__ float blur5(float w0, float w1, float w2, float w3, float w4) {
    const float G0 = 0.13533528323661270f;   // exp(-2)
    const float G1 = 0.60653065971263342f;   // exp(-0.5)
    float a = __fmul_rn(G0, w0);
    a = __fmaf_rn(G1, w1, a);
    a = __fadd_rn(a, w2);
    a = __fmaf_rn(G1, w3, a);
    a = __fmaf_rn(G0, w4, a);
    return a;
}

// identical sobel chains — do not touch
__device__ __forceinline__ void sobel3(float L0, float C0, float R0,
                                       float L1, float R1,
                                       float L2, float C2, float R2,
                                       float& gxv, float& gyv) {
    gxv = L0;
    gxv = __fmaf_rn(-1.0f, R0, gxv);
    gxv = __fmaf_rn( 2.0f, L1, gxv);
    gxv = __fmaf_rn(-2.0f, R1, gxv);
    gxv = __fadd_rn(gxv, L2);
    gxv = __fmaf_rn(-1.0f, R2, gxv);
    gyv = L0;
    gyv = __fmaf_rn( 2.0f, C0, gyv);
    gyv = __fadd_rn(gyv, R0);
    gyv = __fmaf_rn(-1.0f, L2, gyv);
    gyv = __fmaf_rn(-2.0f, C2, gyv);
    gyv = __fmaf_rn(-1.0f, R2, gyv);
}

__device__ __forceinline__ float pick9(int dy, int dx,
                                       float tl, float tc, float tr,
                                       float cl, float cc, float cr,
                                       float bl, float bc, float br) {
    float rl, rc, rr;
    if (dy < 0)      { rl = tl; rc = tc; rr = tr; }
    else if (dy > 0) { rl = bl; rc = bc; rr = br; }
    else             { rl = cl; rc = cc; rr = cr; }
    return (dx < 0) ? rl : ((dx > 0) ? rr : rc);
}

// identical NMS/orientation sequence — do not touch
__device__ __forceinline__ float nms_px(float m, float gxd, float gyd,
                                        float tl, float tc, float tr,
                                        float cl, float cr,
                                        float bl, float bc, float br,
                                        int gy, int gx) {
    float ang = atan2f(gyd, gxd);
    float orient = __fadd_rn(__fmul_rn(ang, 57.295779513082323f), 180.0f);
    float o45 = __fdiv_rn(orient, 45.0f);
    int r = (int)rintf(o45);
    int ip = r & 7;
    int dy = c_dy[ip], dx = c_dx[ip];
    float posn = pick9( dy,  dx, tl, tc, tr, cl, m, cr, bl, bc, br);
    float negn = pick9(-dy, -dx, tl, tc, tr, cl, m, cr, bl, bc, br);
    float pos = __fadd_rn(m, -posn);
    float neg = __fadd_rn(m, -negn);
    float res = (fminf(pos, neg) > 0.0f && m >= 1.0f) ? m : 0.0f;
    if (gy == 0 || gy == IMG_H - 1 || gx == 0 || gx == IMG_W - 1)
        res = 0.0f;
    return res;
}

__global__ __launch_bounds__(128, 4)
void canny_sliding2(const float* __restrict__ img, float* __restrict__ out) {
    const unsigned FULL = 0xffffffffu;
    const int lane  = threadIdx.x & 31;
    const int warp  = threadIdx.x >> 5;
    const int strip = blockIdx.x * WPB + warp;
    if (strip >= NSTRIPS) return;

    const int b   = blockIdx.z;
    const int r0  = blockIdx.y * CHUNK;
    const int col0 = strip * USEFUL - 4 + 2 * lane;       // even; lane owns cols col0, col0+1
    const bool colok = (unsigned)col0 < (unsigned)IMG_W;  // pair fully in or out

    const float* p0 = img + ((size_t)(b * 3 + 0) << 20) + col0;
    const float* p1 = img + ((size_t)(b * 3 + 1) << 20) + col0;
    const float* p2 = img + ((size_t)(b * 3 + 2) << 20) + col0;
    float* po = out + ((size_t)b << 20);

    // register pipeline state
    float2 hb[3][4];                  // hblur rows ri-4..ri-1
    float2 vb[3][2];                  // blurred rows ri-4, ri-3 (own 2 cols)
    float  vL[3][2], vR[3][2];        // blurred left/right neighbor cols
    #pragma unroll
    for (int c = 0; c < 3; c++) {
        #pragma unroll
        for (int j = 0; j < 4; j++) hb[c][j] = make_float2(0.f, 0.f);
        #pragma unroll
        for (int j = 0; j < 2; j++) {
            vb[c][j] = make_float2(0.f, 0.f);
            vL[c][j] = 0.f; vR[c][j] = 0.f;
        }
    }
    float2 mg0 = make_float2(0.f, 0.f), mg1 = make_float2(0.f, 0.f);
    float  mgL0 = 0.f, mgL1 = 0.f, mgR0 = 0.f, mgR1 = 0.f;
    float2 gxd = make_float2(0.f, 0.f), gyd = make_float2(0.f, 0.f);

    // preload input row r0-4
    float2 xc0 = make_float2(0.f, 0.f), xc1 = xc0, xc2 = xc0;
    {
        int ri = r0 - 4;
        if ((unsigned)ri < (unsigned)IMG_H && colok) {
            size_t off = (size_t)ri * IMG_W;
            xc0 = __ldg((const float2*)(p0 + off));
            xc1 = __ldg((const float2*)(p1 + off));
            xc2 = __ldg((const float2*)(p2 + off));
        }
    }

    #pragma unroll 4
    for (int it = 0; it < CHUNK + 8; it++) {
        const int ri = r0 - 4 + it;

        // prefetch next input row
        float2 xn0 = make_float2(0.f, 0.f), xn1 = xn0, xn2 = xn0;
        {
            int rn = ri + 1;
            if ((unsigned)rn < (unsigned)IMG_H && colok) {
                size_t off = (size_t)rn * IMG_W;
                xn0 = __ldg((const float2*)(p0 + off));
                xn1 = __ldg((const float2*)(p1 + off));
                xn2 = __ldg((const float2*)(p2 + off));
            }
        }

        const bool vrowok = (unsigned)(ri - 2) < (unsigned)IMG_H;  // blurred row
        const bool srowok = (unsigned)(ri - 3) < (unsigned)IMG_H;  // sobel/mag row

        float2 mag_new = make_float2(0.f, 0.f);
        float2 gxs = mag_new, gys = mag_new;
        float  mLn_all[3], mRn_all[3];  // unused placeholder removed below
        (void)mLn_all; (void)mRn_all;

        float2 xin[3] = {xc0, xc1, xc2};
        #pragma unroll
        for (int c = 0; c < 3; c++) {
            float2 x = xin[c];
            // neighbor input cols via shuffles
            float pl_lo = __shfl_up_sync  (FULL, x.x, 1);  // col0-2
            float pl_hi = __shfl_up_sync  (FULL, x.y, 1);  // col0-1
            float nx_lo = __shfl_down_sync(FULL, x.x, 1);  // col0+2
            float nx_hi = __shfl_down_sync(FULL, x.y, 1);  // col0+3
            float hb_lo = blur5(pl_lo, pl_hi, x.x, x.y, nx_lo);
            float hb_hi = blur5(pl_hi, x.x, x.y, nx_lo, nx_hi);

            // vertical blur -> blurred row ri-2, masked outside the image
            float vb_lo = blur5(hb[c][0].x, hb[c][1].x, hb[c][2].x, hb[c][3].x, hb_lo);
            float vb_hi = blur5(hb[c][0].y, hb[c][1].y, hb[c][2].y, hb[c][3].y, hb_hi);
            if (!colok || !vrowok) { vb_lo = 0.f; vb_hi = 0.f; }
            hb[c][0] = hb[c][1]; hb[c][1] = hb[c][2];
            hb[c][2] = hb[c][3]; hb[c][3] = make_float2(hb_lo, hb_hi);

            float vLn = __shfl_up_sync  (FULL, vb_hi, 1);  // col0-1
            float vRn = __shfl_down_sync(FULL, vb_lo, 1);  // col0+2

            // sobel at row ri-3 for both pixels
            float gx_lo, gy_lo, gx_hi, gy_hi;
            sobel3(vL[c][0],   vb[c][0].x, vb[c][0].y,
                   vL[c][1],               vb[c][1].y,
                   vLn,        vb_lo,      vb_hi,      gx_lo, gy_lo);
            sobel3(vb[c][0].x, vb[c][0].y, vR[c][0],
                   vb[c][1].x,             vR[c][1],
                   vb_lo,      vb_hi,      vRn,        gx_hi, gy_hi);

            float s_lo = __fadd_rn(__fmul_rn(gx_lo, gx_lo), __fmul_rn(gy_lo, gy_lo));
            s_lo = __fadd_rn(s_lo, 1e-8f);
            float m_lo = __fsqrt_rn(s_lo);
            float s_hi = __fadd_rn(__fmul_rn(gx_hi, gx_hi), __fmul_rn(gy_hi, gy_hi));
            s_hi = __fadd_rn(s_hi, 1e-8f);
            float m_hi = __fsqrt_rn(s_hi);
            if (!srowok || !colok) { m_lo = 0.f; m_hi = 0.f; }

            if (c == 0) {
                mag_new = make_float2(m_lo, m_hi);
                gxs = make_float2(gx_lo, gx_hi);
                gys = make_float2(gy_lo, gy_hi);
            } else {
                mag_new.x = __fadd_rn(mag_new.x, m_lo);
                mag_new.y = __fadd_rn(mag_new.y, m_hi);
                gxs.x = __fadd_rn(gxs.x, gx_lo);
                gxs.y = __fadd_rn(gxs.y, gx_hi);
                gys.x = __fadd_rn(gys.x, gy_lo);
                gys.y = __fadd_rn(gys.y, gy_hi);
            }

            vb[c][0] = vb[c][1]; vb[c][1] = make_float2(vb_lo, vb_hi);
            vL[c][0] = vL[c][1]; vL[c][1] = vLn;
            vR[c][0] = vR[c][1]; vR[c][1] = vRn;
        }

        float mgLn = __shfl_up_sync  (FULL, mag_new.y, 1);  // col0-1
        float mgRn = __shfl_down_sync(FULL, mag_new.x, 1);  // col0+2

        // output row ro = ri-4 (mag rows ro-1, ro, ro+1 = mg0, mg1, mag_new)
        const int ro = ri - 4;
        if (ro >= r0 && lane >= 2 && lane <= 29 && colok) {
            float res_lo = nms_px(mg1.x, gxd.x, gyd.x,
                                  mgL0, mg0.x, mg0.y,
                                  mgL1,        mg1.y,
                                  mgLn, mag_new.x, mag_new.y,
                                  ro, col0);
            float res_hi = nms_px(mg1.y, gxd.y, gyd.y,
                                  mg0.x, mg0.y, mgR0,
                                  mg1.x,        mgR1,
                                  mag_new.x, mag_new.y, mgRn,
                                  ro, col0 + 1);
            *(float2*)&po[(size_t)ro * IMG_W + col0] = make_float2(res_lo, res_hi);
        }

        // slide windows
        mg0 = mg1; mg1 = mag_new;
        mgL0 = mgL1; mgL1 = mgLn;
        mgR0 = mgR1; mgR1 = mgRn;
        gxd = gxs; gyd = gys;
        xc0 = xn0; xc1 = xn1; xc2 = xn2;
    }
}

extern "C" void kernel_launch(void* const* d_in, const int* in_sizes, int n_in,
                              void* d_out, int out_size) {
    const float* img = (const float*)d_in[0];
    float* o = (float*)d_out;
    dim3 grid((NSTRIPS + WPB - 1) / WPB, IMG_H / CHUNK, 8);
    canny_sliding2<<<grid, WPB * 32>>>(img, o);
}